// round 13
// baseline (speedup 1.0000x reference)
#include <cuda_runtime.h>
#include <cuda_fp16.h>
#include <math.h>
#include <stdint.h>

// Problem constants
#define BATCH   4
#define SEQLEN  2048
#define DMODEL  512
#define DSTATE  64
#define MTOT    (BATCH * SEQLEN)   // 8192

// ---------------------------------------------------------------------------
// Device scratch (no cudaMalloc allowed)
// ---------------------------------------------------------------------------
__device__ __half g_uh[BATCH * DMODEL * SEQLEN];  // [b][d][l] u fp16 (gemm1 out)
__device__ __half g_yh[BATCH * DMODEL * SEQLEN];  // [b][d][l] y fp16 (scan out)
__device__ __half g_ah[MTOT * DMODEL];            // x hi [token][k]
__device__ __half g_wh[2 * DMODEL * DMODEL];      // W_in | W_out hi
// chunked-scan operator matrices (per d)
__device__ __half g_R [DMODEL * 64 * 64];         // R[d][n][i]  = r_n^(63-i)
__device__ __half g_Km[DMODEL * 64 * 64];         // Km[d][t][i] = k_d[t-i] (low-tri; k[0]+=D)
__device__ __half g_Qt[DMODEL * 64 * 64];         // Qt[d][t][n] = r_n^(t+1)
__device__ float  g_rho [DMODEL * 64];            // r_n^64
__device__ float  g_coef[DMODEL * 64];            // c_n = C*B*dt

// ---------------------------------------------------------------------------
// PTX helpers
// ---------------------------------------------------------------------------
__device__ __forceinline__ uint32_t smem_u32(const void* p) {
    uint32_t a;
    asm("{ .reg .u64 t; cvta.to.shared.u64 t, %1; cvt.u32.u64 %0, t; }" : "=r"(a) : "l"(p));
    return a;
}
__device__ __forceinline__ void cpasync16(uint32_t s, const void* g) {
    asm volatile("cp.async.cg.shared.global [%0], [%1], 16;" :: "r"(s), "l"(g));
}
__device__ __forceinline__ void cp_commit() {
    asm volatile("cp.async.commit_group;" ::: "memory");
}
__device__ __forceinline__ void ldsm4(uint32_t a, uint32_t* r) {
    asm volatile("ldmatrix.sync.aligned.m8n8.x4.shared.b16 {%0,%1,%2,%3}, [%4];"
                 : "=r"(r[0]), "=r"(r[1]), "=r"(r[2]), "=r"(r[3]) : "r"(a));
}
__device__ __forceinline__ void ldsm4t(uint32_t a, uint32_t* r) {
    asm volatile("ldmatrix.sync.aligned.m8n8.x4.trans.shared.b16 {%0,%1,%2,%3}, [%4];"
                 : "=r"(r[0]), "=r"(r[1]), "=r"(r[2]), "=r"(r[3]) : "r"(a));
}
__device__ __forceinline__ void mma16816(float* c, const uint32_t* a, const uint32_t* b) {
    asm volatile(
        "mma.sync.aligned.m16n8k16.row.col.f32.f16.f16.f32 "
        "{%0,%1,%2,%3}, {%4,%5,%6,%7}, {%8,%9}, {%0,%1,%2,%3};"
        : "+f"(c[0]), "+f"(c[1]), "+f"(c[2]), "+f"(c[3])
        : "r"(a[0]), "r"(a[1]), "r"(a[2]), "r"(a[3]), "r"(b[0]), "r"(b[1]));
}

// ---------------------------------------------------------------------------
// Conversion: x -> fp16 hi; weights -> fp16 hi.
// ---------------------------------------------------------------------------
#define N4_X (MTOT * DMODEL / 4)
#define N4_W (DMODEL * DMODEL / 4)

__global__ __launch_bounds__(256) void convert_all(const float* __restrict__ x,
                                                   const float* __restrict__ w_in,
                                                   const float* __restrict__ w_out,
                                                   __half* __restrict__ ah,
                                                   __half* __restrict__ wh)
{
    int i = blockIdx.x * 256 + threadIdx.x;
    if (i < N4_X) {
        float4 v = ((const float4*)x)[i];
        uint2 ph;
        ph.x = (uint32_t)__half_as_ushort(__float2half_rn(v.x)) |
               ((uint32_t)__half_as_ushort(__float2half_rn(v.y)) << 16);
        ph.y = (uint32_t)__half_as_ushort(__float2half_rn(v.z)) |
               ((uint32_t)__half_as_ushort(__float2half_rn(v.w)) << 16);
        ((uint2*)ah)[i] = ph;
    } else if (i < N4_X + 2 * N4_W) {
        const int off = i - N4_X;
        const float4 v = (off < N4_W) ? ((const float4*)w_in)[off]
                                      : ((const float4*)w_out)[off - N4_W];
        uint2 ph;
        ph.x = (uint32_t)__half_as_ushort(__float2half_rn(v.x)) |
               ((uint32_t)__half_as_ushort(__float2half_rn(v.y)) << 16);
        ph.y = (uint32_t)__half_as_ushort(__float2half_rn(v.z)) |
               ((uint32_t)__half_as_ushort(__float2half_rn(v.w)) << 16);
        ((uint2*)wh)[off] = ph;
    }
}

// ---------------------------------------------------------------------------
// Prep: per-d operator matrices for the chunked scan. One 64-thread CTA per d.
// ---------------------------------------------------------------------------
__global__ __launch_bounds__(64) void s4_prep(const float* __restrict__ A_log,
                                              const float* __restrict__ Bp,
                                              const float* __restrict__ Cp,
                                              const float* __restrict__ Dp,
                                              const float* __restrict__ dt)
{
    __shared__ float Pc[64][65];
    __shared__ float ksm[64];
    const int d = blockIdx.x;
    const int n = threadIdx.x;
    const int idx = d * 64 + n;

    const float dtd = dt[d];
    const float r  = expf(-expf(A_log[idx]) * dtd);
    const float cf = Cp[idx] * Bp[idx] * dtd;
    g_coef[idx] = cf;

    __half* Rrow = g_R + d * 4096 + n * 64;
    float p = 1.0f;
#pragma unroll 1
    for (int tau = 0; tau < 64; tau++) {
        Pc[n][tau] = cf * p;
        Rrow[63 - tau] = __float2half_rn(p);               // R[n][i]=r^(63-i)
        g_Qt[d * 4096 + tau * 64 + n] = __float2half_rn(p * r);  // Qt[t][n]=r^(t+1)
        p *= r;
    }
    g_rho[idx] = p;   // r^64
    __syncthreads();

    // k[tau] = sum_n cf_n r_n^tau  (+D at tau=0); thread index = tau here
    float k = 0.0f;
#pragma unroll 1
    for (int nn = 0; nn < 64; nn++) k += Pc[nn][n];
    if (n == 0) k += Dp[d];
    ksm[n] = k;
    __syncthreads();

    // Km[t][i] = k[t-i] for i<=t else 0; thread index = t
    __half* Krow = g_Km + d * 4096 + n * 64;
#pragma unroll 1
    for (int i = 0; i < 64; i++)
        Krow[i] = (i <= n) ? __float2half_rn(ksm[n - i]) : __half(0.0f);
}

// ---------------------------------------------------------------------------
// GEMM config: CTA tile 128(M) x 256(N), K-chunk 128, 4 chunks, 2 stages.
// 16 warps 4x4, warp tile 32x64. Single wave (128 CTAs).
// ---------------------------------------------------------------------------
#define NTHREADS 512
#define STAGE_BYTES 98304
#define SMEM_BYTES  (2 * STAGE_BYTES)   // 192 KB

// ---------------------------------------------------------------------------
// GEMM1 (in_proj): D[d, token] = sum_k Wh[d,k] * xh[token,k]
// Epilogue -> g_uh[b][d][l] fp16.
// ---------------------------------------------------------------------------
__global__ __launch_bounds__(NTHREADS, 1) void gemm_mma1(const __half* __restrict__ Wh,
                                                         const __half* __restrict__ Xh,
                                                         const float* __restrict__ bias)
{
    extern __shared__ __align__(1024) char dyn[];
    const uint32_t sb = smem_u32(dyn);
    const int tid  = threadIdx.x;
    const int wid  = tid >> 5;
    const int lane = tid & 31;
    const int wm = wid & 3;
    const int wn = wid >> 2;
    const int n0 = blockIdx.x * 256; // token
    const int m0 = blockIdx.y * 128; // d

    const __half* Ah = Wh + (size_t)m0 * 512;
    const __half* Bh = Xh + (size_t)n0 * 512;

    auto load_stage = [&](int stage, int c) {
        const int k0 = c * 128;
        const uint32_t sbase = sb + stage * STAGE_BYTES;
#pragma unroll
        for (int i = 0; i < 8; i++) {
            const int idx = i * NTHREADS + tid;
            const int r  = idx >> 4;
            const int ch = idx & 15;
            const uint32_t so = (uint32_t)(r * 256 + ((ch ^ (r & 7)) << 4));
            const size_t  go = (size_t)r * 512 + k0 + ch * 8;
            cpasync16(sbase + 32768 + so, Bh + go);
            if (i < 4) cpasync16(sbase + so, Ah + go);
        }
        cp_commit();
    };

    float c[2][8][4];
#pragma unroll
    for (int mi = 0; mi < 2; mi++)
#pragma unroll
        for (int ni = 0; ni < 8; ni++)
#pragma unroll
            for (int j = 0; j < 4; j++) c[mi][ni][j] = 0.0f;

    load_stage(0, 0);
    load_stage(1, 1);

    const int grp = lane >> 3;
    const int sub = lane & 7;

#pragma unroll 1
    for (int cch = 0; cch < 4; cch++) {
        if (cch == 3) asm volatile("cp.async.wait_group 0;" ::: "memory");
        else          asm volatile("cp.async.wait_group 1;" ::: "memory");
        __syncthreads();

        const uint32_t sa = sb + (cch & 1) * STAGE_BYTES;

#pragma unroll
        for (int s = 0; s < 8; s++) {
            uint32_t aH[2][4];
#pragma unroll
            for (int mi = 0; mi < 2; mi++) {
                const int rowA = wm * 32 + mi * 16 + (grp & 1) * 8 + sub;
                const int kcA  = s * 2 + (grp >> 1);
                const uint32_t off = (uint32_t)(rowA * 256 + ((kcA ^ (rowA & 7)) << 4));
                ldsm4(sa + off, aH[mi]);
            }
#pragma unroll
            for (int p = 0; p < 4; p++) {
                uint32_t bH[4];
                const int rowB = wn * 64 + (2 * p + (grp >> 1)) * 8 + sub;
                const int kcB  = s * 2 + (grp & 1);
                const uint32_t off = (uint32_t)(rowB * 256 + ((kcB ^ (rowB & 7)) << 4));
                ldsm4(sa + 32768 + off, bH);
#pragma unroll
                for (int mi = 0; mi < 2; mi++) {
                    mma16816(c[mi][2 * p + 0], aH[mi], &bH[0]);
                    mma16816(c[mi][2 * p + 1], aH[mi], &bH[2]);
                }
            }
        }
        __syncthreads();
        if (cch + 2 < 4) load_stage(cch & 1, cch + 2);
    }

    // epilogue: m=d rows, n=token cols -> g_uh[b][d][l] fp16
    const int q  = lane >> 2;
    const int t2 = (lane & 3) * 2;
    const int b  = n0 >> 11;
    const int lt = (n0 & 2047) + wn * 64;
#pragma unroll
    for (int mi = 0; mi < 2; mi++)
#pragma unroll
        for (int rr = 0; rr < 2; rr++) {
            const int d_row = m0 + wm * 32 + mi * 16 + rr * 8 + q;
            const float bi = __ldg(bias + d_row);
            __half* dst = g_uh + ((size_t)(b * DMODEL + d_row) << 11) + lt;
#pragma unroll
            for (int ni = 0; ni < 8; ni++) {
                *(__half2*)(dst + ni * 8 + t2) =
                    __floats2half2_rn(c[mi][ni][rr * 2 + 0] + bi,
                                      c[mi][ni][rr * 2 + 1] + bi);
            }
        }
}

// ---------------------------------------------------------------------------
// Chunked SSM scan on tensor cores. One 256-thread CTA per d.
//   S  = U @ R^T          [128 x 64]   (chunk end-state contributions)
//   z-recurrence over 32 chunks per b (fp32, trivial); Z''[c,n] = c_n*z_before
//   Y  = U @ Km^T + Z'' @ Qt^T  -> g_yh
// ---------------------------------------------------------------------------
#define SC_U 0
#define SC_R 16384
#define SC_K 24576
#define SC_Q 32768
#define SC_Z 40960
#define SC_S 57344
#define SC_SMEM 90112

__global__ __launch_bounds__(256, 1) void s4_scan_tc()
{
    extern __shared__ __align__(1024) char dyn[];
    const uint32_t sb = smem_u32(dyn);
    const int tid  = threadIdx.x;
    const int wid  = tid >> 5;       // 8 warps; warp w -> rows 16w..16w+15
    const int lane = tid & 31;
    const int d = blockIdx.x;
    const int grp = lane >> 3;
    const int sub = lane & 7;

    // ---- load U (128x64), R, Km, Qt (64x64 each) into swizzled smem ----
#pragma unroll
    for (int i = 0; i < 4; i++) {
        const int idx = i * 256 + tid;          // 0..1023
        const int r  = idx >> 3;
        const int ch = idx & 7;
        const uint32_t so = (uint32_t)(r * 128 + ((ch ^ (r & 7)) << 4));
        cpasync16(sb + SC_U + so,
                  g_uh + (((size_t)((r >> 5) * DMODEL + d)) << 11) + (r & 31) * 64 + ch * 8);
        if (i < 2) {
            cpasync16(sb + SC_R + so, g_R  + d * 4096 + r * 64 + ch * 8);
            cpasync16(sb + SC_K + so, g_Km + d * 4096 + r * 64 + ch * 8);
            cpasync16(sb + SC_Q + so, g_Qt + d * 4096 + r * 64 + ch * 8);
        }
    }
    cp_commit();
    asm volatile("cp.async.wait_group 0;" ::: "memory");
    __syncthreads();

    float acc[8][4];
#pragma unroll
    for (int ni = 0; ni < 8; ni++)
#pragma unroll
        for (int j = 0; j < 4; j++) acc[ni][j] = 0.0f;

    // ---- Phase S: S[c,n] = sum_i U[c,i] * R[n,i] ----
#pragma unroll
    for (int s = 0; s < 4; s++) {
        uint32_t aH[4];
        const int rowA = wid * 16 + (grp & 1) * 8 + sub;
        const int kcA  = s * 2 + (grp >> 1);
        ldsm4(sb + SC_U + (uint32_t)(rowA * 128 + ((kcA ^ (rowA & 7)) << 4)), aH);
#pragma unroll
        for (int p = 0; p < 4; p++) {
            uint32_t bH[4];
            const int rowB = (2 * p + (grp >> 1)) * 8 + sub;
            const int kcB  = s * 2 + (grp & 1);
            ldsm4(sb + SC_R + (uint32_t)(rowB * 128 + ((kcB ^ (rowB & 7)) << 4)), bH);
            mma16816(acc[2 * p + 0], aH, &bH[0]);
            mma16816(acc[2 * p + 1], aH, &bH[2]);
        }
    }
    // write S (fp32) to smem [row][64]
    {
        float* Ssm = (float*)(dyn + SC_S);
        const int q  = lane >> 2;
        const int t2 = (lane & 3) * 2;
#pragma unroll
        for (int rr = 0; rr < 2; rr++) {
            const int row = wid * 16 + rr * 8 + q;
#pragma unroll
            for (int ni = 0; ni < 8; ni++) {
                Ssm[row * 64 + ni * 8 + t2 + 0] = acc[ni][rr * 2 + 0];
                Ssm[row * 64 + ni * 8 + t2 + 1] = acc[ni][rr * 2 + 1];
            }
        }
    }
    __syncthreads();

    // ---- z-recurrence: thread = (b, n); Z''[c,n] = c_n * z_before(c) ----
    {
        const float* Ssm = (const float*)(dyn + SC_S);
        const int b = tid >> 6;
        const int n = tid & 63;
        const float rho = g_rho[d * 64 + n];
        const float cf  = g_coef[d * 64 + n];
        float z = 0.0f;
#pragma unroll 1
        for (int c2 = 0; c2 < 32; c2++) {
            const int row = b * 32 + c2;
            // swizzled fp16 store into Z buffer (same layout as U)
            *(__half*)(dyn + SC_Z + row * 128 + (((n >> 3) ^ (row & 7)) << 4) + (n & 7) * 2) =
                __float2half_rn(cf * z);
            z = fmaf(rho, z, Ssm[row * 64 + n]);
        }
    }
    __syncthreads();

    // ---- Phase Y: Y = U @ Km^T + Z'' @ Qt^T ----
#pragma unroll
    for (int ni = 0; ni < 8; ni++)
#pragma unroll
        for (int j = 0; j < 4; j++) acc[ni][j] = 0.0f;

#pragma unroll
    for (int pass = 0; pass < 2; pass++) {
        const uint32_t abase = sb + (pass ? SC_Z : SC_U);
        const uint32_t bbase = sb + (pass ? SC_Q : SC_K);
#pragma unroll
        for (int s = 0; s < 4; s++) {
            uint32_t aH[4];
            const int rowA = wid * 16 + (grp & 1) * 8 + sub;
            const int kcA  = s * 2 + (grp >> 1);
            ldsm4(abase + (uint32_t)(rowA * 128 + ((kcA ^ (rowA & 7)) << 4)), aH);
#pragma unroll
            for (int p = 0; p < 4; p++) {
                uint32_t bH[4];
                const int rowB = (2 * p + (grp >> 1)) * 8 + sub;
                const int kcB  = s * 2 + (grp & 1);
                ldsm4(bbase + (uint32_t)(rowB * 128 + ((kcB ^ (rowB & 7)) << 4)), bH);
                mma16816(acc[2 * p + 0], aH, &bH[0]);
                mma16816(acc[2 * p + 1], aH, &bH[2]);
            }
        }
    }

    // ---- epilogue: y -> g_yh[b][d][c*64+t] fp16 ----
    {
        const int q  = lane >> 2;
        const int t2 = (lane & 3) * 2;
#pragma unroll
        for (int rr = 0; rr < 2; rr++) {
            const int row = wid * 16 + rr * 8 + q;     // = b*32 + c
            const int b = row >> 5;
            __half* dst = g_yh + ((size_t)(b * DMODEL + d) << 11) + (row & 31) * 64;
#pragma unroll
            for (int ni = 0; ni < 8; ni++) {
                *(__half2*)(dst + ni * 8 + t2) =
                    __floats2half2_rn(acc[ni][rr * 2 + 0], acc[ni][rr * 2 + 1]);
            }
        }
    }
}

// ---------------------------------------------------------------------------
// GEMM2 (out_proj): out[token, n] = sum_k yh[token,k] * Wh[n,k]
// A = y-hi from K-major [b][d][l] via ldmatrix.trans; [128 k][128 m] tile.
// ---------------------------------------------------------------------------
__global__ __launch_bounds__(NTHREADS, 1) void gemm_mma2(const __half* __restrict__ Wh,
                                                         const float* __restrict__ bias,
                                                         float* __restrict__ Cout)
{
    extern __shared__ __align__(1024) char dyn[];
    const uint32_t sb = smem_u32(dyn);
    const int tid  = threadIdx.x;
    const int wid  = tid >> 5;
    const int lane = tid & 31;
    const int wm = wid & 3;
    const int wn = wid >> 2;
    const int n0 = blockIdx.x * 256;   // d_out
    const int m0 = blockIdx.y * 128;   // token
    const int b    = m0 >> 11;
    const int ltok = m0 & 2047;

    const __half* Bh = Wh + (size_t)n0 * 512;

    auto load_stage = [&](int stage, int c) {
        const int k0 = c * 128;
        const uint32_t sbase = sb + stage * STAGE_BYTES;
#pragma unroll
        for (int i = 0; i < 8; i++) {
            const int idx = i * NTHREADS + tid;
            const int rB  = idx >> 4;
            const int chB = idx & 15;
            const uint32_t soB = (uint32_t)(rB * 256 + ((chB ^ (rB & 7)) << 4));
            const size_t  goB = (size_t)rB * 512 + k0 + chB * 8;
            cpasync16(sbase + 32768 + soB, Bh + goB);
            if (i < 4) {
                cpasync16(sbase + soB,
                          g_yh + (((size_t)(b * DMODEL + k0 + rB)) << 11) + ltok + chB * 8);
            }
        }
        cp_commit();
    };

    float c[2][8][4];
#pragma unroll
    for (int mi = 0; mi < 2; mi++)
#pragma unroll
        for (int ni = 0; ni < 8; ni++)
#pragma unroll
            for (int j = 0; j < 4; j++) c[mi][ni][j] = 0.0f;

    load_stage(0, 0);
    load_stage(1, 1);

    const int grp = lane >> 3;
    const int sub = lane & 7;

#pragma unroll 1
    for (int cch = 0; cch < 4; cch++) {
        if (cch == 3) asm volatile("cp.async.wait_group 0;" ::: "memory");
        else          asm volatile("cp.async.wait_group 1;" ::: "memory");
        __syncthreads();

        const uint32_t sa = sb + (cch & 1) * STAGE_BYTES;

#pragma unroll
        for (int s = 0; s < 8; s++) {
            uint32_t aH[2][4];
#pragma unroll
            for (int mi = 0; mi < 2; mi++) {
                const int krow = s * 16 + (grp >> 1) * 8 + sub;
                const int mcol = wm * 32 + mi * 16 + (grp & 1) * 8;
                const int chunk = mcol >> 3;
                const uint32_t off = (uint32_t)(krow * 256 + ((chunk ^ (krow & 7)) << 4));
                ldsm4t(sa + off, aH[mi]);
            }
#pragma unroll
            for (int p = 0; p < 4; p++) {
                uint32_t bH[4];
                const int rowB = wn * 64 + (2 * p + (grp >> 1)) * 8 + sub;
                const int kcB  = s * 2 + (grp & 1);
                const uint32_t off = (uint32_t)(rowB * 256 + ((kcB ^ (rowB & 7)) << 4));
                ldsm4(sa + 32768 + off, bH);
#pragma unroll
                for (int mi = 0; mi < 2; mi++) {
                    mma16816(c[mi][2 * p + 0], aH[mi], &bH[0]);
                    mma16816(c[mi][2 * p + 1], aH[mi], &bH[2]);
                }
            }
        }
        __syncthreads();
        if (cch + 2 < 4) load_stage(cch & 1, cch + 2);
    }

    const int q  = lane >> 2;
    const int t2 = (lane & 3) * 2;
#pragma unroll
    for (int mi = 0; mi < 2; mi++)
#pragma unroll
        for (int rr = 0; rr < 2; rr++) {
            const int row = m0 + wm * 32 + mi * 16 + rr * 8 + q;
            float* dst = Cout + (size_t)row * 512 + n0 + wn * 64;
#pragma unroll
            for (int ni = 0; ni < 8; ni++) {
                const float2 bv = *(const float2*)(bias + n0 + wn * 64 + ni * 8 + t2);
                float2 v;
                v.x = c[mi][ni][rr * 2 + 0] + bv.x;
                v.y = c[mi][ni][rr * 2 + 1] + bv.y;
                *(float2*)(dst + ni * 8 + t2) = v;
            }
        }
}

// ---------------------------------------------------------------------------
extern "C" void kernel_launch(void* const* d_in, const int* in_sizes, int n_in,
                              void* d_out, int out_size)
{
    const float* x     = (const float*)d_in[0];
    const float* W_in  = (const float*)d_in[1];
    const float* b_in  = (const float*)d_in[2];
    const float* A_log = (const float*)d_in[3];
    const float* B     = (const float*)d_in[4];
    const float* C     = (const float*)d_in[5];
    const float* D     = (const float*)d_in[6];
    const float* dt    = (const float*)d_in[7];
    const float* W_out = (const float*)d_in[8];
    const float* b_out = (const float*)d_in[9];
    float* out = (float*)d_out;

    static bool attr_done = false;
    if (!attr_done) {
        cudaFuncSetAttribute(gemm_mma1, cudaFuncAttributeMaxDynamicSharedMemorySize, SMEM_BYTES);
        cudaFuncSetAttribute(gemm_mma2, cudaFuncAttributeMaxDynamicSharedMemorySize, SMEM_BYTES);
        cudaFuncSetAttribute(s4_scan_tc, cudaFuncAttributeMaxDynamicSharedMemorySize, SC_SMEM);
        attr_done = true;
    }

    __half *p_ah, *p_wh;
    cudaGetSymbolAddress((void**)&p_ah, g_ah);
    cudaGetSymbolAddress((void**)&p_wh, g_wh);

    // 1) convert inputs + weights to fp16
    {
        const int total = N4_X + 2 * N4_W;
        convert_all<<<(total + 255) / 256, 256>>>(x, W_in, W_out, p_ah, p_wh);
    }

    // 2) prep chunked-scan operator matrices (independent of convert/gemm1)
    s4_prep<<<DMODEL, 64>>>(A_log, B, C, D, dt);

    // 3) in_proj: D[d, token] -> g_uh[b][d][l] fp16
    {
        dim3 g(MTOT / 256, DMODEL / 128);
        gemm_mma1<<<g, NTHREADS, SMEM_BYTES>>>(p_wh, p_ah, b_in);
    }

    // 4) chunked SSM scan on tensor cores: g_uh -> g_yh
    s4_scan_tc<<<DMODEL, 256, SC_SMEM>>>();

    // 5) out_proj: yh (trans) @ W_out_h^T -> out
    {
        dim3 g(DMODEL / 256, MTOT / 128);
        gemm_mma2<<<g, NTHREADS, SMEM_BYTES>>>(p_wh + DMODEL * DMODEL, b_out, out);
    }
}

// round 15
// speedup vs baseline: 1.0012x; 1.0012x over previous
#include <cuda_runtime.h>
#include <cuda_fp16.h>
#include <math.h>
#include <stdint.h>

// Problem constants
#define BATCH   4
#define SEQLEN  2048
#define DMODEL  512
#define DSTATE  64
#define MTOT    (BATCH * SEQLEN)   // 8192

// ---------------------------------------------------------------------------
// Device scratch (no cudaMalloc allowed)
// ---------------------------------------------------------------------------
__device__ __half g_uh[BATCH * DMODEL * SEQLEN];  // [b][d][l] u fp16 (gemm1 out)
__device__ __half g_yh[BATCH * DMODEL * SEQLEN];  // [b][d][l] y fp16 (scan out)
__device__ __half g_ah[MTOT * DMODEL];            // x hi [token][k]
__device__ __half g_wh[2 * DMODEL * DMODEL];      // W_in | W_out hi
// chunked-scan operator matrices (per d)
__device__ __half g_R [DMODEL * 64 * 64];         // R[d][n][i]  = r_n^(63-i)
__device__ __half g_Km[DMODEL * 64 * 64];         // Km[d][t][i] = k_d[t-i] (low-tri; k[0]+=D)
__device__ __half g_Qt[DMODEL * 64 * 64];         // Qt[d][t][n] = r_n^(t+1)
__device__ float  g_rho [DMODEL * 64];            // r_n^64
__device__ float  g_coef[DMODEL * 64];            // c_n = C*B*dt

// ---------------------------------------------------------------------------
// PTX helpers
// ---------------------------------------------------------------------------
__device__ __forceinline__ uint32_t smem_u32(const void* p) {
    uint32_t a;
    asm("{ .reg .u64 t; cvta.to.shared.u64 t, %1; cvt.u32.u64 %0, t; }" : "=r"(a) : "l"(p));
    return a;
}
__device__ __forceinline__ void cpasync16(uint32_t s, const void* g) {
    asm volatile("cp.async.cg.shared.global [%0], [%1], 16;" :: "r"(s), "l"(g));
}
__device__ __forceinline__ void cp_commit() {
    asm volatile("cp.async.commit_group;" ::: "memory");
}
__device__ __forceinline__ void ldsm4(uint32_t a, uint32_t* r) {
    asm volatile("ldmatrix.sync.aligned.m8n8.x4.shared.b16 {%0,%1,%2,%3}, [%4];"
                 : "=r"(r[0]), "=r"(r[1]), "=r"(r[2]), "=r"(r[3]) : "r"(a));
}
__device__ __forceinline__ void ldsm4t(uint32_t a, uint32_t* r) {
    asm volatile("ldmatrix.sync.aligned.m8n8.x4.trans.shared.b16 {%0,%1,%2,%3}, [%4];"
                 : "=r"(r[0]), "=r"(r[1]), "=r"(r[2]), "=r"(r[3]) : "r"(a));
}
__device__ __forceinline__ void mma16816(float* c, const uint32_t* a, const uint32_t* b) {
    asm volatile(
        "mma.sync.aligned.m16n8k16.row.col.f32.f16.f16.f32 "
        "{%0,%1,%2,%3}, {%4,%5,%6,%7}, {%8,%9}, {%0,%1,%2,%3};"
        : "+f"(c[0]), "+f"(c[1]), "+f"(c[2]), "+f"(c[3])
        : "r"(a[0]), "r"(a[1]), "r"(a[2]), "r"(a[3]), "r"(b[0]), "r"(b[1]));
}

// ---------------------------------------------------------------------------
// Conversion: x -> fp16 hi; weights -> fp16 hi.
// ---------------------------------------------------------------------------
#define N4_X (MTOT * DMODEL / 4)
#define N4_W (DMODEL * DMODEL / 4)

__global__ __launch_bounds__(256) void convert_all(const float* __restrict__ x,
                                                   const float* __restrict__ w_in,
                                                   const float* __restrict__ w_out,
                                                   __half* __restrict__ ah,
                                                   __half* __restrict__ wh)
{
    int i = blockIdx.x * 256 + threadIdx.x;
    if (i < N4_X) {
        float4 v = ((const float4*)x)[i];
        uint2 ph;
        ph.x = (uint32_t)__half_as_ushort(__float2half_rn(v.x)) |
               ((uint32_t)__half_as_ushort(__float2half_rn(v.y)) << 16);
        ph.y = (uint32_t)__half_as_ushort(__float2half_rn(v.z)) |
               ((uint32_t)__half_as_ushort(__float2half_rn(v.w)) << 16);
        ((uint2*)ah)[i] = ph;
    } else if (i < N4_X + 2 * N4_W) {
        const int off = i - N4_X;
        const float4 v = (off < N4_W) ? ((const float4*)w_in)[off]
                                      : ((const float4*)w_out)[off - N4_W];
        uint2 ph;
        ph.x = (uint32_t)__half_as_ushort(__float2half_rn(v.x)) |
               ((uint32_t)__half_as_ushort(__float2half_rn(v.y)) << 16);
        ph.y = (uint32_t)__half_as_ushort(__float2half_rn(v.z)) |
               ((uint32_t)__half_as_ushort(__float2half_rn(v.w)) << 16);
        ((uint2*)wh)[off] = ph;
    }
}

// ---------------------------------------------------------------------------
// Prep: per-d operator matrices for the chunked scan. One 64-thread CTA per d.
// ---------------------------------------------------------------------------
__global__ __launch_bounds__(64) void s4_prep(const float* __restrict__ A_log,
                                              const float* __restrict__ Bp,
                                              const float* __restrict__ Cp,
                                              const float* __restrict__ Dp,
                                              const float* __restrict__ dt)
{
    __shared__ float Pc[64][65];
    __shared__ float ksm[64];
    const int d = blockIdx.x;
    const int n = threadIdx.x;
    const int idx = d * 64 + n;

    const float dtd = dt[d];
    const float r  = expf(-expf(A_log[idx]) * dtd);
    const float cf = Cp[idx] * Bp[idx] * dtd;
    g_coef[idx] = cf;

    __half* Rrow = g_R + d * 4096 + n * 64;
    float p = 1.0f;
#pragma unroll 1
    for (int tau = 0; tau < 64; tau++) {
        Pc[n][tau] = cf * p;
        Rrow[63 - tau] = __float2half_rn(p);               // R[n][i]=r^(63-i)
        g_Qt[d * 4096 + tau * 64 + n] = __float2half_rn(p * r);  // Qt[t][n]=r^(t+1)
        p *= r;
    }
    g_rho[idx] = p;   // r^64
    __syncthreads();

    // k[tau] = sum_n cf_n r_n^tau  (+D at tau=0); thread index = tau here
    float k = 0.0f;
#pragma unroll 1
    for (int nn = 0; nn < 64; nn++) k += Pc[nn][n];
    if (n == 0) k += Dp[d];
    ksm[n] = k;
    __syncthreads();

    // Km[t][i] = k[t-i] for i<=t else 0; thread index = t
    __half* Krow = g_Km + d * 4096 + n * 64;
#pragma unroll 1
    for (int i = 0; i < 64; i++)
        Krow[i] = (i <= n) ? __float2half_rn(ksm[n - i]) : __half(0.0f);
}

// ---------------------------------------------------------------------------
// GEMM config: CTA tile 128(M) x 256(N), K-chunk 128, 4 chunks, 2 stages.
// 16 warps 4x4, warp tile 32x64. Single wave (128 CTAs).
// ---------------------------------------------------------------------------
#define NTHREADS 512
#define STAGE_BYTES 98304
#define SMEM_BYTES  (2 * STAGE_BYTES)   // 192 KB

// ---------------------------------------------------------------------------
// GEMM1 (in_proj): D[d, token] = sum_k Wh[d,k] * xh[token,k]
// Epilogue -> g_uh[b][d][l] fp16.
// ---------------------------------------------------------------------------
__global__ __launch_bounds__(NTHREADS, 1) void gemm_mma1(const __half* __restrict__ Wh,
                                                         const __half* __restrict__ Xh,
                                                         const float* __restrict__ bias)
{
    extern __shared__ __align__(1024) char dyn[];
    const uint32_t sb = smem_u32(dyn);
    const int tid  = threadIdx.x;
    const int wid  = tid >> 5;
    const int lane = tid & 31;
    const int wm = wid & 3;
    const int wn = wid >> 2;
    const int n0 = blockIdx.x * 256; // token
    const int m0 = blockIdx.y * 128; // d

    const __half* Ah = Wh + (size_t)m0 * 512;
    const __half* Bh = Xh + (size_t)n0 * 512;

    auto load_stage = [&](int stage, int c) {
        const int k0 = c * 128;
        const uint32_t sbase = sb + stage * STAGE_BYTES;
#pragma unroll
        for (int i = 0; i < 8; i++) {
            const int idx = i * NTHREADS + tid;
            const int r  = idx >> 4;
            const int ch = idx & 15;
            const uint32_t so = (uint32_t)(r * 256 + ((ch ^ (r & 7)) << 4));
            const size_t  go = (size_t)r * 512 + k0 + ch * 8;
            cpasync16(sbase + 32768 + so, Bh + go);
            if (i < 4) cpasync16(sbase + so, Ah + go);
        }
        cp_commit();
    };

    float c[2][8][4];
#pragma unroll
    for (int mi = 0; mi < 2; mi++)
#pragma unroll
        for (int ni = 0; ni < 8; ni++)
#pragma unroll
            for (int j = 0; j < 4; j++) c[mi][ni][j] = 0.0f;

    load_stage(0, 0);
    load_stage(1, 1);

    const int grp = lane >> 3;
    const int sub = lane & 7;

#pragma unroll 1
    for (int cch = 0; cch < 4; cch++) {
        if (cch == 3) asm volatile("cp.async.wait_group 0;" ::: "memory");
        else          asm volatile("cp.async.wait_group 1;" ::: "memory");
        __syncthreads();

        const uint32_t sa = sb + (cch & 1) * STAGE_BYTES;

#pragma unroll
        for (int s = 0; s < 8; s++) {
            uint32_t aH[2][4];
#pragma unroll
            for (int mi = 0; mi < 2; mi++) {
                const int rowA = wm * 32 + mi * 16 + (grp & 1) * 8 + sub;
                const int kcA  = s * 2 + (grp >> 1);
                const uint32_t off = (uint32_t)(rowA * 256 + ((kcA ^ (rowA & 7)) << 4));
                ldsm4(sa + off, aH[mi]);
            }
#pragma unroll
            for (int p = 0; p < 4; p++) {
                uint32_t bH[4];
                const int rowB = wn * 64 + (2 * p + (grp >> 1)) * 8 + sub;
                const int kcB  = s * 2 + (grp & 1);
                const uint32_t off = (uint32_t)(rowB * 256 + ((kcB ^ (rowB & 7)) << 4));
                ldsm4(sa + 32768 + off, bH);
#pragma unroll
                for (int mi = 0; mi < 2; mi++) {
                    mma16816(c[mi][2 * p + 0], aH[mi], &bH[0]);
                    mma16816(c[mi][2 * p + 1], aH[mi], &bH[2]);
                }
            }
        }
        __syncthreads();
        if (cch + 2 < 4) load_stage(cch & 1, cch + 2);
    }

    // epilogue: m=d rows, n=token cols -> g_uh[b][d][l] fp16
    const int q  = lane >> 2;
    const int t2 = (lane & 3) * 2;
    const int b  = n0 >> 11;
    const int lt = (n0 & 2047) + wn * 64;
#pragma unroll
    for (int mi = 0; mi < 2; mi++)
#pragma unroll
        for (int rr = 0; rr < 2; rr++) {
            const int d_row = m0 + wm * 32 + mi * 16 + rr * 8 + q;
            const float bi = __ldg(bias + d_row);
            __half* dst = g_uh + ((size_t)(b * DMODEL + d_row) << 11) + lt;
#pragma unroll
            for (int ni = 0; ni < 8; ni++) {
                *(__half2*)(dst + ni * 8 + t2) =
                    __floats2half2_rn(c[mi][ni][rr * 2 + 0] + bi,
                                      c[mi][ni][rr * 2 + 1] + bi);
            }
        }
}

// ---------------------------------------------------------------------------
// Chunked SSM scan on tensor cores. One 256-thread CTA per d.
//   S  = U @ R^T          [128 x 64]   (chunk end-state contributions)
//   z-recurrence over 32 chunks per b (fp32, trivial); Z''[c,n] = c_n*z_before
//   Y  = U @ Km^T + Z'' @ Qt^T  -> g_yh
// ---------------------------------------------------------------------------
#define SC_U 0
#define SC_R 16384
#define SC_K 24576
#define SC_Q 32768
#define SC_Z 40960
#define SC_S 57344
#define SC_SMEM 90112

__global__ __launch_bounds__(256, 1) void s4_scan_tc()
{
    extern __shared__ __align__(1024) char dyn[];
    const uint32_t sb = smem_u32(dyn);
    const int tid  = threadIdx.x;
    const int wid  = tid >> 5;       // 8 warps; warp w -> rows 16w..16w+15
    const int lane = tid & 31;
    const int d = blockIdx.x;
    const int grp = lane >> 3;
    const int sub = lane & 7;

    // ---- load U (128x64), R, Km, Qt (64x64 each) into swizzled smem ----
#pragma unroll
    for (int i = 0; i < 4; i++) {
        const int idx = i * 256 + tid;          // 0..1023
        const int r  = idx >> 3;
        const int ch = idx & 7;
        const uint32_t so = (uint32_t)(r * 128 + ((ch ^ (r & 7)) << 4));
        cpasync16(sb + SC_U + so,
                  g_uh + (((size_t)((r >> 5) * DMODEL + d)) << 11) + (r & 31) * 64 + ch * 8);
        if (i < 2) {
            cpasync16(sb + SC_R + so, g_R  + d * 4096 + r * 64 + ch * 8);
            cpasync16(sb + SC_K + so, g_Km + d * 4096 + r * 64 + ch * 8);
            cpasync16(sb + SC_Q + so, g_Qt + d * 4096 + r * 64 + ch * 8);
        }
    }
    cp_commit();
    asm volatile("cp.async.wait_group 0;" ::: "memory");
    __syncthreads();

    float acc[8][4];
#pragma unroll
    for (int ni = 0; ni < 8; ni++)
#pragma unroll
        for (int j = 0; j < 4; j++) acc[ni][j] = 0.0f;

    // ---- Phase S: S[c,n] = sum_i U[c,i] * R[n,i] ----
#pragma unroll
    for (int s = 0; s < 4; s++) {
        uint32_t aH[4];
        const int rowA = wid * 16 + (grp & 1) * 8 + sub;
        const int kcA  = s * 2 + (grp >> 1);
        ldsm4(sb + SC_U + (uint32_t)(rowA * 128 + ((kcA ^ (rowA & 7)) << 4)), aH);
#pragma unroll
        for (int p = 0; p < 4; p++) {
            uint32_t bH[4];
            const int rowB = (2 * p + (grp >> 1)) * 8 + sub;
            const int kcB  = s * 2 + (grp & 1);
            ldsm4(sb + SC_R + (uint32_t)(rowB * 128 + ((kcB ^ (rowB & 7)) << 4)), bH);
            mma16816(acc[2 * p + 0], aH, &bH[0]);
            mma16816(acc[2 * p + 1], aH, &bH[2]);
        }
    }
    // write S (fp32) to smem [row][64]
    {
        float* Ssm = (float*)(dyn + SC_S);
        const int q  = lane >> 2;
        const int t2 = (lane & 3) * 2;
#pragma unroll
        for (int rr = 0; rr < 2; rr++) {
            const int row = wid * 16 + rr * 8 + q;
#pragma unroll
            for (int ni = 0; ni < 8; ni++) {
                Ssm[row * 64 + ni * 8 + t2 + 0] = acc[ni][rr * 2 + 0];
                Ssm[row * 64 + ni * 8 + t2 + 1] = acc[ni][rr * 2 + 1];
            }
        }
    }
    __syncthreads();

    // ---- z-recurrence: thread = (b, n); Z''[c,n] = c_n * z_before(c) ----
    {
        const float* Ssm = (const float*)(dyn + SC_S);
        const int b = tid >> 6;
        const int n = tid & 63;
        const float rho = g_rho[d * 64 + n];
        const float cf  = g_coef[d * 64 + n];
        float z = 0.0f;
#pragma unroll 1
        for (int c2 = 0; c2 < 32; c2++) {
            const int row = b * 32 + c2;
            // swizzled fp16 store into Z buffer (same layout as U)
            *(__half*)(dyn + SC_Z + row * 128 + (((n >> 3) ^ (row & 7)) << 4) + (n & 7) * 2) =
                __float2half_rn(cf * z);
            z = fmaf(rho, z, Ssm[row * 64 + n]);
        }
    }
    __syncthreads();

    // ---- Phase Y: Y = U @ Km^T + Z'' @ Qt^T ----
#pragma unroll
    for (int ni = 0; ni < 8; ni++)
#pragma unroll
        for (int j = 0; j < 4; j++) acc[ni][j] = 0.0f;

#pragma unroll
    for (int pass = 0; pass < 2; pass++) {
        const uint32_t abase = sb + (pass ? SC_Z : SC_U);
        const uint32_t bbase = sb + (pass ? SC_Q : SC_K);
#pragma unroll
        for (int s = 0; s < 4; s++) {
            uint32_t aH[4];
            const int rowA = wid * 16 + (grp & 1) * 8 + sub;
            const int kcA  = s * 2 + (grp >> 1);
            ldsm4(abase + (uint32_t)(rowA * 128 + ((kcA ^ (rowA & 7)) << 4)), aH);
#pragma unroll
            for (int p = 0; p < 4; p++) {
                uint32_t bH[4];
                const int rowB = (2 * p + (grp >> 1)) * 8 + sub;
                const int kcB  = s * 2 + (grp & 1);
                ldsm4(bbase + (uint32_t)(rowB * 128 + ((kcB ^ (rowB & 7)) << 4)), bH);
                mma16816(acc[2 * p + 0], aH, &bH[0]);
                mma16816(acc[2 * p + 1], aH, &bH[2]);
            }
        }
    }

    // ---- epilogue: y -> g_yh[b][d][c*64+t] fp16 ----
    {
        const int q  = lane >> 2;
        const int t2 = (lane & 3) * 2;
#pragma unroll
        for (int rr = 0; rr < 2; rr++) {
            const int row = wid * 16 + rr * 8 + q;     // = b*32 + c
            const int b = row >> 5;
            __half* dst = g_yh + ((size_t)(b * DMODEL + d) << 11) + (row & 31) * 64;
#pragma unroll
            for (int ni = 0; ni < 8; ni++) {
                *(__half2*)(dst + ni * 8 + t2) =
                    __floats2half2_rn(acc[ni][rr * 2 + 0], acc[ni][rr * 2 + 1]);
            }
        }
    }
}

// ---------------------------------------------------------------------------
// GEMM2 (out_proj): out[token, n] = sum_k yh[token,k] * Wh[n,k]
// A = y-hi from K-major [b][d][l] via ldmatrix.trans; [128 k][128 m] tile.
// ---------------------------------------------------------------------------
__global__ __launch_bounds__(NTHREADS, 1) void gemm_mma2(const __half* __restrict__ Wh,
                                                         const float* __restrict__ bias,
                                                         float* __restrict__ Cout)
{
    extern __shared__ __align__(1024) char dyn[];
    const uint32_t sb = smem_u32(dyn);
    const int tid  = threadIdx.x;
    const int wid  = tid >> 5;
    const int lane = tid & 31;
    const int wm = wid & 3;
    const int wn = wid >> 2;
    const int n0 = blockIdx.x * 256;   // d_out
    const int m0 = blockIdx.y * 128;   // token
    const int b    = m0 >> 11;
    const int ltok = m0 & 2047;

    const __half* Bh = Wh + (size_t)n0 * 512;

    auto load_stage = [&](int stage, int c) {
        const int k0 = c * 128;
        const uint32_t sbase = sb + stage * STAGE_BYTES;
#pragma unroll
        for (int i = 0; i < 8; i++) {
            const int idx = i * NTHREADS + tid;
            const int rB  = idx >> 4;
            const int chB = idx & 15;
            const uint32_t soB = (uint32_t)(rB * 256 + ((chB ^ (rB & 7)) << 4));
            const size_t  goB = (size_t)rB * 512 + k0 + chB * 8;
            cpasync16(sbase + 32768 + soB, Bh + goB);
            if (i < 4) {
                cpasync16(sbase + soB,
                          g_yh + (((size_t)(b * DMODEL + k0 + rB)) << 11) + ltok + chB * 8);
            }
        }
        cp_commit();
    };

    float c[2][8][4];
#pragma unroll
    for (int mi = 0; mi < 2; mi++)
#pragma unroll
        for (int ni = 0; ni < 8; ni++)
#pragma unroll
            for (int j = 0; j < 4; j++) c[mi][ni][j] = 0.0f;

    load_stage(0, 0);
    load_stage(1, 1);

    const int grp = lane >> 3;
    const int sub = lane & 7;

#pragma unroll 1
    for (int cch = 0; cch < 4; cch++) {
        if (cch == 3) asm volatile("cp.async.wait_group 0;" ::: "memory");
        else          asm volatile("cp.async.wait_group 1;" ::: "memory");
        __syncthreads();

        const uint32_t sa = sb + (cch & 1) * STAGE_BYTES;

#pragma unroll
        for (int s = 0; s < 8; s++) {
            uint32_t aH[2][4];
#pragma unroll
            for (int mi = 0; mi < 2; mi++) {
                const int krow = s * 16 + (grp >> 1) * 8 + sub;
                const int mcol = wm * 32 + mi * 16 + (grp & 1) * 8;
                const int chunk = mcol >> 3;
                const uint32_t off = (uint32_t)(krow * 256 + ((chunk ^ (krow & 7)) << 4));
                ldsm4t(sa + off, aH[mi]);
            }
#pragma unroll
            for (int p = 0; p < 4; p++) {
                uint32_t bH[4];
                const int rowB = wn * 64 + (2 * p + (grp >> 1)) * 8 + sub;
                const int kcB  = s * 2 + (grp & 1);
                const uint32_t off = (uint32_t)(rowB * 256 + ((kcB ^ (rowB & 7)) << 4));
                ldsm4(sa + 32768 + off, bH);
#pragma unroll
                for (int mi = 0; mi < 2; mi++) {
                    mma16816(c[mi][2 * p + 0], aH[mi], &bH[0]);
                    mma16816(c[mi][2 * p + 1], aH[mi], &bH[2]);
                }
            }
        }
        __syncthreads();
        if (cch + 2 < 4) load_stage(cch & 1, cch + 2);
    }

    const int q  = lane >> 2;
    const int t2 = (lane & 3) * 2;
#pragma unroll
    for (int mi = 0; mi < 2; mi++)
#pragma unroll
        for (int rr = 0; rr < 2; rr++) {
            const int row = m0 + wm * 32 + mi * 16 + rr * 8 + q;
            float* dst = Cout + (size_t)row * 512 + n0 + wn * 64;
#pragma unroll
            for (int ni = 0; ni < 8; ni++) {
                const float2 bv = *(const float2*)(bias + n0 + wn * 64 + ni * 8 + t2);
                float2 v;
                v.x = c[mi][ni][rr * 2 + 0] + bv.x;
                v.y = c[mi][ni][rr * 2 + 1] + bv.y;
                *(float2*)(dst + ni * 8 + t2) = v;
            }
        }
}

// ---------------------------------------------------------------------------
extern "C" void kernel_launch(void* const* d_in, const int* in_sizes, int n_in,
                              void* d_out, int out_size)
{
    const float* x     = (const float*)d_in[0];
    const float* W_in  = (const float*)d_in[1];
    const float* b_in  = (const float*)d_in[2];
    const float* A_log = (const float*)d_in[3];
    const float* B     = (const float*)d_in[4];
    const float* C     = (const float*)d_in[5];
    const float* D     = (const float*)d_in[6];
    const float* dt    = (const float*)d_in[7];
    const float* W_out = (const float*)d_in[8];
    const float* b_out = (const float*)d_in[9];
    float* out = (float*)d_out;

    static bool attr_done = false;
    if (!attr_done) {
        cudaFuncSetAttribute(gemm_mma1, cudaFuncAttributeMaxDynamicSharedMemorySize, SMEM_BYTES);
        cudaFuncSetAttribute(gemm_mma2, cudaFuncAttributeMaxDynamicSharedMemorySize, SMEM_BYTES);
        cudaFuncSetAttribute(s4_scan_tc, cudaFuncAttributeMaxDynamicSharedMemorySize, SC_SMEM);
        attr_done = true;
    }

    __half *p_ah, *p_wh;
    cudaGetSymbolAddress((void**)&p_ah, g_ah);
    cudaGetSymbolAddress((void**)&p_wh, g_wh);

    // 1) convert inputs + weights to fp16
    {
        const int total = N4_X + 2 * N4_W;
        convert_all<<<(total + 255) / 256, 256>>>(x, W_in, W_out, p_ah, p_wh);
    }

    // 2) prep chunked-scan operator matrices (independent of convert/gemm1)
    s4_prep<<<DMODEL, 64>>>(A_log, B, C, D, dt);

    // 3) in_proj: D[d, token] -> g_uh[b][d][l] fp16
    {
        dim3 g(MTOT / 256, DMODEL / 128);
        gemm_mma1<<<g, NTHREADS, SMEM_BYTES>>>(p_wh, p_ah, b_in);
    }

    // 4) chunked SSM scan on tensor cores: g_uh -> g_yh
    s4_scan_tc<<<DMODEL, 256, SC_SMEM>>>();

    // 5) out_proj: yh (trans) @ W_out_h^T -> out
    {
        dim3 g(DMODEL / 256, MTOT / 128);
        gemm_mma2<<<g, NTHREADS, SMEM_BYTES>>>(p_wh + DMODEL * DMODEL, b_out, out);
    }
}

// round 17
// speedup vs baseline: 1.6679x; 1.6658x over previous
#include <cuda_runtime.h>
#include <cuda_fp16.h>
#include <math.h>
#include <stdint.h>

// Problem constants
#define BATCH   4
#define SEQLEN  2048
#define DMODEL  512
#define DSTATE  64
#define MTOT    (BATCH * SEQLEN)   // 8192

// ---------------------------------------------------------------------------
// Device scratch (no cudaMalloc allowed)
// ---------------------------------------------------------------------------
__device__ __half g_uh[BATCH * DMODEL * SEQLEN];  // [b][d][l] u fp16 (gemm1 out)
__device__ __half g_yh[BATCH * DMODEL * SEQLEN];  // [b][d][l] y fp16 (scan out)
__device__ __half g_ah[MTOT * DMODEL];            // x hi [token][k]
__device__ __half g_wh[2 * DMODEL * DMODEL];      // W_in | W_out hi

// ---------------------------------------------------------------------------
// PTX helpers
// ---------------------------------------------------------------------------
__device__ __forceinline__ uint32_t smem_u32(const void* p) {
    uint32_t a;
    asm("{ .reg .u64 t; cvta.to.shared.u64 t, %1; cvt.u32.u64 %0, t; }" : "=r"(a) : "l"(p));
    return a;
}
__device__ __forceinline__ void cpasync16(uint32_t s, const void* g) {
    asm volatile("cp.async.cg.shared.global [%0], [%1], 16;" :: "r"(s), "l"(g));
}
__device__ __forceinline__ void cp_commit() {
    asm volatile("cp.async.commit_group;" ::: "memory");
}
__device__ __forceinline__ void ldsm4(uint32_t a, uint32_t* r) {
    asm volatile("ldmatrix.sync.aligned.m8n8.x4.shared.b16 {%0,%1,%2,%3}, [%4];"
                 : "=r"(r[0]), "=r"(r[1]), "=r"(r[2]), "=r"(r[3]) : "r"(a));
}
__device__ __forceinline__ void ldsm4t(uint32_t a, uint32_t* r) {
    asm volatile("ldmatrix.sync.aligned.m8n8.x4.trans.shared.b16 {%0,%1,%2,%3}, [%4];"
                 : "=r"(r[0]), "=r"(r[1]), "=r"(r[2]), "=r"(r[3]) : "r"(a));
}
__device__ __forceinline__ void mma16816(float* c, const uint32_t* a, const uint32_t* b) {
    asm volatile(
        "mma.sync.aligned.m16n8k16.row.col.f32.f16.f16.f32 "
        "{%0,%1,%2,%3}, {%4,%5,%6,%7}, {%8,%9}, {%0,%1,%2,%3};"
        : "+f"(c[0]), "+f"(c[1]), "+f"(c[2]), "+f"(c[3])
        : "r"(a[0]), "r"(a[1]), "r"(a[2]), "r"(a[3]), "r"(b[0]), "r"(b[1]));
}

// swizzled fp16 element address within a [rows][64] half tile (128B rows)
__device__ __forceinline__ uint32_t sw_h(int row, int col) {
    return (uint32_t)(row * 128 + (((col >> 3) ^ (row & 7)) << 4) + (col & 7) * 2);
}

// ---------------------------------------------------------------------------
// Conversion: x -> fp16 hi; weights -> fp16 hi.
// ---------------------------------------------------------------------------
#define N4_X (MTOT * DMODEL / 4)
#define N4_W (DMODEL * DMODEL / 4)

__global__ __launch_bounds__(256) void convert_all(const float* __restrict__ x,
                                                   const float* __restrict__ w_in,
                                                   const float* __restrict__ w_out,
                                                   __half* __restrict__ ah,
                                                   __half* __restrict__ wh)
{
    int i = blockIdx.x * 256 + threadIdx.x;
    if (i < N4_X) {
        float4 v = ((const float4*)x)[i];
        uint2 ph;
        ph.x = (uint32_t)__half_as_ushort(__float2half_rn(v.x)) |
               ((uint32_t)__half_as_ushort(__float2half_rn(v.y)) << 16);
        ph.y = (uint32_t)__half_as_ushort(__float2half_rn(v.z)) |
               ((uint32_t)__half_as_ushort(__float2half_rn(v.w)) << 16);
        ((uint2*)ah)[i] = ph;
    } else if (i < N4_X + 2 * N4_W) {
        const int off = i - N4_X;
        const float4 v = (off < N4_W) ? ((const float4*)w_in)[off]
                                      : ((const float4*)w_out)[off - N4_W];
        uint2 ph;
        ph.x = (uint32_t)__half_as_ushort(__float2half_rn(v.x)) |
               ((uint32_t)__half_as_ushort(__float2half_rn(v.y)) << 16);
        ph.y = (uint32_t)__half_as_ushort(__float2half_rn(v.z)) |
               ((uint32_t)__half_as_ushort(__float2half_rn(v.w)) << 16);
        ((uint2*)wh)[off] = ph;
    }
}

// ---------------------------------------------------------------------------
// GEMM config: CTA tile 128(M) x 256(N), K-chunk 128, 4 chunks, 2 stages.
// ---------------------------------------------------------------------------
#define NTHREADS 512
#define STAGE_BYTES 98304
#define SMEM_BYTES  (2 * STAGE_BYTES)   // 192 KB

// ---------------------------------------------------------------------------
// GEMM1 (in_proj): D[d, token] = sum_k Wh[d,k] * xh[token,k] -> g_uh fp16
// ---------------------------------------------------------------------------
__global__ __launch_bounds__(NTHREADS, 1) void gemm_mma1(const __half* __restrict__ Wh,
                                                         const __half* __restrict__ Xh,
                                                         const float* __restrict__ bias)
{
    extern __shared__ __align__(1024) char dyn[];
    const uint32_t sb = smem_u32(dyn);
    const int tid  = threadIdx.x;
    const int wid  = tid >> 5;
    const int lane = tid & 31;
    const int wm = wid & 3;
    const int wn = wid >> 2;
    const int n0 = blockIdx.x * 256; // token
    const int m0 = blockIdx.y * 128; // d

    const __half* Ah = Wh + (size_t)m0 * 512;
    const __half* Bh = Xh + (size_t)n0 * 512;

    auto load_stage = [&](int stage, int c) {
        const int k0 = c * 128;
        const uint32_t sbase = sb + stage * STAGE_BYTES;
#pragma unroll
        for (int i = 0; i < 8; i++) {
            const int idx = i * NTHREADS + tid;
            const int r  = idx >> 4;
            const int ch = idx & 15;
            const uint32_t so = (uint32_t)(r * 256 + ((ch ^ (r & 7)) << 4));
            const size_t  go = (size_t)r * 512 + k0 + ch * 8;
            cpasync16(sbase + 32768 + so, Bh + go);
            if (i < 4) cpasync16(sbase + so, Ah + go);
        }
        cp_commit();
    };

    float c[2][8][4];
#pragma unroll
    for (int mi = 0; mi < 2; mi++)
#pragma unroll
        for (int ni = 0; ni < 8; ni++)
#pragma unroll
            for (int j = 0; j < 4; j++) c[mi][ni][j] = 0.0f;

    load_stage(0, 0);
    load_stage(1, 1);

    const int grp = lane >> 3;
    const int sub = lane & 7;

#pragma unroll 1
    for (int cch = 0; cch < 4; cch++) {
        if (cch == 3) asm volatile("cp.async.wait_group 0;" ::: "memory");
        else          asm volatile("cp.async.wait_group 1;" ::: "memory");
        __syncthreads();

        const uint32_t sa = sb + (cch & 1) * STAGE_BYTES;

#pragma unroll
        for (int s = 0; s < 8; s++) {
            uint32_t aH[2][4];
#pragma unroll
            for (int mi = 0; mi < 2; mi++) {
                const int rowA = wm * 32 + mi * 16 + (grp & 1) * 8 + sub;
                const int kcA  = s * 2 + (grp >> 1);
                const uint32_t off = (uint32_t)(rowA * 256 + ((kcA ^ (rowA & 7)) << 4));
                ldsm4(sa + off, aH[mi]);
            }
#pragma unroll
            for (int p = 0; p < 4; p++) {
                uint32_t bH[4];
                const int rowB = wn * 64 + (2 * p + (grp >> 1)) * 8 + sub;
                const int kcB  = s * 2 + (grp & 1);
                const uint32_t off = (uint32_t)(rowB * 256 + ((kcB ^ (rowB & 7)) << 4));
                ldsm4(sa + 32768 + off, bH);
#pragma unroll
                for (int mi = 0; mi < 2; mi++) {
                    mma16816(c[mi][2 * p + 0], aH[mi], &bH[0]);
                    mma16816(c[mi][2 * p + 1], aH[mi], &bH[2]);
                }
            }
        }
        __syncthreads();
        if (cch + 2 < 4) load_stage(cch & 1, cch + 2);
    }

    const int q  = lane >> 2;
    const int t2 = (lane & 3) * 2;
    const int b  = n0 >> 11;
    const int lt = (n0 & 2047) + wn * 64;
#pragma unroll
    for (int mi = 0; mi < 2; mi++)
#pragma unroll
        for (int rr = 0; rr < 2; rr++) {
            const int d_row = m0 + wm * 32 + mi * 16 + rr * 8 + q;
            const float bi = __ldg(bias + d_row);
            __half* dst = g_uh + ((size_t)(b * DMODEL + d_row) << 11) + lt;
#pragma unroll
            for (int ni = 0; ni < 8; ni++) {
                *(__half2*)(dst + ni * 8 + t2) =
                    __floats2half2_rn(c[mi][ni][rr * 2 + 0] + bi,
                                      c[mi][ni][rr * 2 + 1] + bi);
            }
        }
}

// ---------------------------------------------------------------------------
// Chunked SSM scan on tensor cores, operator matrices built IN-CTA.
// One 256-thread CTA per d.
// SMEM map (NO overlaps):
//   U  [128x64 h]  @     0 .. 16384
//   R  [ 64x64 h]  @ 16384 .. 24576
//   Km [ 64x64 h]  @ 24576 .. 32768
//   Qt [ 64x64 h]  @ 32768 .. 40960
//   Z  [128x64 h]  @ 40960 .. 57344   (16 KB!)
//   S  [128x64 f]  @ 57344 .. 90112   (also Pf [64][65] f during prep)
//   misc (256 f)   @ 90112 .. 91136
// ---------------------------------------------------------------------------
#define SC_U 0
#define SC_R 16384
#define SC_K 24576
#define SC_Q 32768
#define SC_Z 40960
#define SC_S 57344
#define SC_MISC 90112
#define SC_SMEM 91136

__global__ __launch_bounds__(256, 1) void s4_scan_tc(const float* __restrict__ A_log,
                                                     const float* __restrict__ Bp,
                                                     const float* __restrict__ Cp,
                                                     const float* __restrict__ Dp,
                                                     const float* __restrict__ dt)
{
    extern __shared__ __align__(1024) char dyn[];
    const uint32_t sb = smem_u32(dyn);
    const int tid  = threadIdx.x;
    const int wid  = tid >> 5;
    const int lane = tid & 31;
    const int d = blockIdx.x;
    const int grp = lane >> 3;
    const int sub = lane & 7;

    float* rr  = (float*)(dyn + SC_MISC);        // [64] r_n
    float* cc  = rr + 64;                        // [64] c_n
    float* rho = cc + 64;                        // [64] r_n^64
    float* ksm = rho + 64;                       // [64] k[tau]

    // ---- kick off U load (overlaps with prep compute) ----
#pragma unroll
    for (int i = 0; i < 4; i++) {
        const int idx = i * 256 + tid;          // 0..1023
        const int r  = idx >> 3;
        const int ch = idx & 7;
        const uint32_t so = (uint32_t)(r * 128 + ((ch ^ (r & 7)) << 4));
        cpasync16(sb + SC_U + so,
                  g_uh + (((size_t)((r >> 5) * DMODEL + d)) << 11) + (r & 31) * 64 + ch * 8);
    }
    cp_commit();

    // ---- prep step 0: r_n, c_n ----
    if (tid < 64) {
        const float dtd = dt[d];
        const float r  = expf(-expf(A_log[d * 64 + tid]) * dtd);
        rr[tid] = r;
        cc[tid] = Cp[d * 64 + tid] * Bp[d * 64 + tid] * dtd;
    }
    __syncthreads();

    // ---- prep step 1: powers. thread=(n,q): tau in [16q,16q+16) ----
    {
        float* Pf = (float*)(dyn + SC_S);        // [64][65] fp32
        const int n = tid >> 2;
        const int qq = tid & 3;
        const float r = rr[n];
        const float r2 = r * r, r4 = r2 * r2, r8 = r4 * r4, r16 = r8 * r8;
        const float r32 = r16 * r16;
        float p = 1.0f;
        if (qq & 1) p *= r16;
        if (qq & 2) p *= r32;                    // p = r^(16q)
#pragma unroll
        for (int j = 0; j < 16; j++) {
            const int tau = qq * 16 + j;
            Pf[n * 65 + tau] = p;
            *(__half*)(dyn + SC_R + sw_h(n, 63 - tau)) = __float2half_rn(p);       // R
            *(__half*)(dyn + SC_Q + sw_h(tau, n))      = __float2half_rn(p * r);   // Qt
            p *= r;
        }
        if (qq == 3) rho[n] = p;                 // r^64
    }
    __syncthreads();

    // ---- prep step 2: k[tau] = sum_n c_n r_n^tau (+D at 0) ----
    if (tid < 64) {
        const float* Pf = (const float*)(dyn + SC_S);
        float k = 0.0f;
#pragma unroll 1
        for (int nn = 0; nn < 64; nn++) k = fmaf(cc[nn], Pf[nn * 65 + tid], k);
        if (tid == 0) k += Dp[d];
        ksm[tid] = k;
    }
    __syncthreads();

    // ---- prep step 3: Km[t][i] = k[t-i] (low-tri). 16 elems/thread ----
    {
        const int t = tid >> 2;
        const int ib = (tid & 3) * 16;
#pragma unroll
        for (int j = 0; j < 16; j++) {
            const int i = ib + j;
            const __half v = (i <= t) ? __float2half_rn(ksm[t - i]) : __half(0.0f);
            *(__half*)(dyn + SC_K + sw_h(t, i)) = v;
        }
    }

    // ---- wait for U, then Phase S ----
    asm volatile("cp.async.wait_group 0;" ::: "memory");
    __syncthreads();

    float acc[8][4];
#pragma unroll
    for (int ni = 0; ni < 8; ni++)
#pragma unroll
        for (int j = 0; j < 4; j++) acc[ni][j] = 0.0f;

    // S[c,n] = sum_i U[c,i] * R[n,i]
#pragma unroll
    for (int s = 0; s < 4; s++) {
        uint32_t aH[4];
        const int rowA = wid * 16 + (grp & 1) * 8 + sub;
        const int kcA  = s * 2 + (grp >> 1);
        ldsm4(sb + SC_U + (uint32_t)(rowA * 128 + ((kcA ^ (rowA & 7)) << 4)), aH);
#pragma unroll
        for (int p = 0; p < 4; p++) {
            uint32_t bH[4];
            const int rowB = (2 * p + (grp >> 1)) * 8 + sub;
            const int kcB  = s * 2 + (grp & 1);
            ldsm4(sb + SC_R + (uint32_t)(rowB * 128 + ((kcB ^ (rowB & 7)) << 4)), bH);
            mma16816(acc[2 * p + 0], aH, &bH[0]);
            mma16816(acc[2 * p + 1], aH, &bH[2]);
        }
    }
    __syncthreads();   // Pf is dead; SC_S region now reusable for Ssm
    {
        float* Ssm = (float*)(dyn + SC_S);
        const int q  = lane >> 2;
        const int t2 = (lane & 3) * 2;
#pragma unroll
        for (int rr2 = 0; rr2 < 2; rr2++) {
            const int row = wid * 16 + rr2 * 8 + q;
#pragma unroll
            for (int ni = 0; ni < 8; ni++) {
                Ssm[row * 64 + ni * 8 + t2 + 0] = acc[ni][rr2 * 2 + 0];
                Ssm[row * 64 + ni * 8 + t2 + 1] = acc[ni][rr2 * 2 + 1];
            }
        }
    }
    __syncthreads();

    // ---- z-recurrence: thread=(b,n); Z''[c,n] = c_n * z_before(c) ----
    {
        const float* Ssm = (const float*)(dyn + SC_S);
        const int b = tid >> 6;
        const int n = tid & 63;
        const float rh = rho[n];
        const float cf = cc[n];
        float z = 0.0f;
#pragma unroll 1
        for (int c2 = 0; c2 < 32; c2++) {
            const int row = b * 32 + c2;
            *(__half*)(dyn + SC_Z + sw_h(row, n)) = __float2half_rn(cf * z);
            z = fmaf(rh, z, Ssm[row * 64 + n]);
        }
    }
    __syncthreads();

    // ---- Phase Y: Y = U @ Km^T + Z'' @ Qt^T ----
#pragma unroll
    for (int ni = 0; ni < 8; ni++)
#pragma unroll
        for (int j = 0; j < 4; j++) acc[ni][j] = 0.0f;

#pragma unroll
    for (int pass = 0; pass < 2; pass++) {
        const uint32_t abase = sb + (pass ? SC_Z : SC_U);
        const uint32_t bbase = sb + (pass ? SC_Q : SC_K);
#pragma unroll
        for (int s = 0; s < 4; s++) {
            uint32_t aH[4];
            const int rowA = wid * 16 + (grp & 1) * 8 + sub;
            const int kcA  = s * 2 + (grp >> 1);
            ldsm4(abase + (uint32_t)(rowA * 128 + ((kcA ^ (rowA & 7)) << 4)), aH);
#pragma unroll
            for (int p = 0; p < 4; p++) {
                uint32_t bH[4];
                const int rowB = (2 * p + (grp >> 1)) * 8 + sub;
                const int kcB  = s * 2 + (grp & 1);
                ldsm4(bbase + (uint32_t)(rowB * 128 + ((kcB ^ (rowB & 7)) << 4)), bH);
                mma16816(acc[2 * p + 0], aH, &bH[0]);
                mma16816(acc[2 * p + 1], aH, &bH[2]);
            }
        }
    }

    // ---- epilogue: y -> g_yh[b][d][c*64+t] fp16 ----
    {
        const int q  = lane >> 2;
        const int t2 = (lane & 3) * 2;
#pragma unroll
        for (int rr2 = 0; rr2 < 2; rr2++) {
            const int row = wid * 16 + rr2 * 8 + q;     // = b*32 + c
            const int b = row >> 5;
            __half* dst = g_yh + ((size_t)(b * DMODEL + d) << 11) + (row & 31) * 64;
#pragma unroll
            for (int ni = 0; ni < 8; ni++) {
                *(__half2*)(dst + ni * 8 + t2) =
                    __floats2half2_rn(acc[ni][rr2 * 2 + 0], acc[ni][rr2 * 2 + 1]);
            }
        }
    }
}

// ---------------------------------------------------------------------------
// GEMM2 (out_proj): out[token, n] = sum_k yh[token,k] * Wh[n,k]
// ---------------------------------------------------------------------------
__global__ __launch_bounds__(NTHREADS, 1) void gemm_mma2(const __half* __restrict__ Wh,
                                                         const float* __restrict__ bias,
                                                         float* __restrict__ Cout)
{
    extern __shared__ __align__(1024) char dyn[];
    const uint32_t sb = smem_u32(dyn);
    const int tid  = threadIdx.x;
    const int wid  = tid >> 5;
    const int lane = tid & 31;
    const int wm = wid & 3;
    const int wn = wid >> 2;
    const int n0 = blockIdx.x * 256;   // d_out
    const int m0 = blockIdx.y * 128;   // token
    const int b    = m0 >> 11;
    const int ltok = m0 & 2047;

    const __half* Bh = Wh + (size_t)n0 * 512;

    auto load_stage = [&](int stage, int c) {
        const int k0 = c * 128;
        const uint32_t sbase = sb + stage * STAGE_BYTES;
#pragma unroll
        for (int i = 0; i < 8; i++) {
            const int idx = i * NTHREADS + tid;
            const int rB  = idx >> 4;
            const int chB = idx & 15;
            const uint32_t soB = (uint32_t)(rB * 256 + ((chB ^ (rB & 7)) << 4));
            const size_t  goB = (size_t)rB * 512 + k0 + chB * 8;
            cpasync16(sbase + 32768 + soB, Bh + goB);
            if (i < 4) {
                cpasync16(sbase + soB,
                          g_yh + (((size_t)(b * DMODEL + k0 + rB)) << 11) + ltok + chB * 8);
            }
        }
        cp_commit();
    };

    float c[2][8][4];
#pragma unroll
    for (int mi = 0; mi < 2; mi++)
#pragma unroll
        for (int ni = 0; ni < 8; ni++)
#pragma unroll
            for (int j = 0; j < 4; j++) c[mi][ni][j] = 0.0f;

    load_stage(0, 0);
    load_stage(1, 1);

    const int grp = lane >> 3;
    const int sub = lane & 7;

#pragma unroll 1
    for (int cch = 0; cch < 4; cch++) {
        if (cch == 3) asm volatile("cp.async.wait_group 0;" ::: "memory");
        else          asm volatile("cp.async.wait_group 1;" ::: "memory");
        __syncthreads();

        const uint32_t sa = sb + (cch & 1) * STAGE_BYTES;

#pragma unroll
        for (int s = 0; s < 8; s++) {
            uint32_t aH[2][4];
#pragma unroll
            for (int mi = 0; mi < 2; mi++) {
                const int krow = s * 16 + (grp >> 1) * 8 + sub;
                const int mcol = wm * 32 + mi * 16 + (grp & 1) * 8;
                const int chunk = mcol >> 3;
                const uint32_t off = (uint32_t)(krow * 256 + ((chunk ^ (krow & 7)) << 4));
                ldsm4t(sa + off, aH[mi]);
            }
#pragma unroll
            for (int p = 0; p < 4; p++) {
                uint32_t bH[4];
                const int rowB = wn * 64 + (2 * p + (grp >> 1)) * 8 + sub;
                const int kcB  = s * 2 + (grp & 1);
                const uint32_t off = (uint32_t)(rowB * 256 + ((kcB ^ (rowB & 7)) << 4));
                ldsm4(sa + 32768 + off, bH);
#pragma unroll
                for (int mi = 0; mi < 2; mi++) {
                    mma16816(c[mi][2 * p + 0], aH[mi], &bH[0]);
                    mma16816(c[mi][2 * p + 1], aH[mi], &bH[2]);
                }
            }
        }
        __syncthreads();
        if (cch + 2 < 4) load_stage(cch & 1, cch + 2);
    }

    const int q  = lane >> 2;
    const int t2 = (lane & 3) * 2;
#pragma unroll
    for (int mi = 0; mi < 2; mi++)
#pragma unroll
        for (int rr = 0; rr < 2; rr++) {
            const int row = m0 + wm * 32 + mi * 16 + rr * 8 + q;
            float* dst = Cout + (size_t)row * 512 + n0 + wn * 64;
#pragma unroll
            for (int ni = 0; ni < 8; ni++) {
                const float2 bv = *(const float2*)(bias + n0 + wn * 64 + ni * 8 + t2);
                float2 v;
                v.x = c[mi][ni][rr * 2 + 0] + bv.x;
                v.y = c[mi][ni][rr * 2 + 1] + bv.y;
                *(float2*)(dst + ni * 8 + t2) = v;
            }
        }
}

// ---------------------------------------------------------------------------
extern "C" void kernel_launch(void* const* d_in, const int* in_sizes, int n_in,
                              void* d_out, int out_size)
{
    const float* x     = (const float*)d_in[0];
    const float* W_in  = (const float*)d_in[1];
    const float* b_in  = (const float*)d_in[2];
    const float* A_log = (const float*)d_in[3];
    const float* B     = (const float*)d_in[4];
    const float* C     = (const float*)d_in[5];
    const float* D     = (const float*)d_in[6];
    const float* dt    = (const float*)d_in[7];
    const float* W_out = (const float*)d_in[8];
    const float* b_out = (const float*)d_in[9];
    float* out = (float*)d_out;

    static bool attr_done = false;
    if (!attr_done) {
        cudaFuncSetAttribute(gemm_mma1, cudaFuncAttributeMaxDynamicSharedMemorySize, SMEM_BYTES);
        cudaFuncSetAttribute(gemm_mma2, cudaFuncAttributeMaxDynamicSharedMemorySize, SMEM_BYTES);
        cudaFuncSetAttribute(s4_scan_tc, cudaFuncAttributeMaxDynamicSharedMemorySize, SC_SMEM);
        attr_done = true;
    }

    __half *p_ah, *p_wh;
    cudaGetSymbolAddress((void**)&p_ah, g_ah);
    cudaGetSymbolAddress((void**)&p_wh, g_wh);

    // 1) convert inputs + weights to fp16
    {
        const int total = N4_X + 2 * N4_W;
        convert_all<<<(total + 255) / 256, 256>>>(x, W_in, W_out, p_ah, p_wh);
    }

    // 2) in_proj: D[d, token] -> g_uh[b][d][l] fp16
    {
        dim3 g(MTOT / 256, DMODEL / 128);
        gemm_mma1<<<g, NTHREADS, SMEM_BYTES>>>(p_wh, p_ah, b_in);
    }

    // 3) chunked SSM scan on tensor cores (operator prep fused): g_uh -> g_yh
    s4_scan_tc<<<DMODEL, 256, SC_SMEM>>>(A_log, B, C, D, dt);

    // 4) out_proj: yh (trans) @ W_out_h^T -> out
    {
        dim3 g(DMODEL / 256, MTOT / 128);
        gemm_mma2<<<g, NTHREADS, SMEM_BYTES>>>(p_wh + DMODEL * DMODEL, b_out, out);
    }
}